// round 13
// baseline (speedup 1.0000x reference)
#include <cuda_runtime.h>
#include <cuda_bf16.h>
#include <cstdint>
#include <cstddef>

#define BB 128
#define TT 2048
#define II 64
#define HH 128
#define GG 512                 // 4*H
#define BT (BB * TT)

// ---- recurrence config: 256 threads, 2 rows/thread --------------------------
#define REGK 112               // W_hh cols per row held in registers
#define SMEMK (HH - REGK)      // 16 cols in SMEM
#define NSQ (SMEMK / 4)        // 4 ulonglong2 groups per row

typedef unsigned long long u64;

// 512MB scratch for x_proj[row][g], row = b*T + t, g in [0,512)
__device__ float g_xproj[(size_t)BT * GG];

__device__ __forceinline__ u64 pk(float lo, float hi) {
    u64 r; asm("mov.b64 %0,{%1,%2};" : "=l"(r) : "f"(lo), "f"(hi)); return r;
}
__device__ __forceinline__ void upk(u64 v, float& lo, float& hi) {
    asm("mov.b64 {%0,%1},%2;" : "=f"(lo), "=f"(hi) : "l"(v));
}
// packed fp32x2 FMA (sm_103a): d.lo += a.lo*b.lo ; d.hi += a.hi*b.hi
__device__ __forceinline__ void fma2(u64& d, u64 a, u64 b) {
    asm("fma.rn.f32x2 %0,%1,%2,%0;" : "+l"(d) : "l"(a), "l"(b));
}

// HW tanh (MUFU-class single op, rel err ~2^-10.8)
__device__ __forceinline__ float tanh_ap(float x) {
    float y; asm("tanh.approx.f32 %0, %1;" : "=f"(y) : "f"(x)); return y;
}
__device__ __forceinline__ float sigmoid_ap(float x) {
    return fmaf(0.5f, tanh_ap(0.5f * x), 0.5f);
}

// ---------------------------------------------------------------------------
// Phase 1: g_xproj[row][512] = W_ih @ x[row] + (b_ih + b_hh)
// Persistent CTAs; W_ih k-major in SMEM; 64-row x tiles k-major in SMEM.
// Weights loaded as ulonglong2 (pre-paired f32x2, no repack MOVs).
// ---------------------------------------------------------------------------
__global__ __launch_bounds__(512, 1) void xproj_kernel(
    const float* __restrict__ x, const float* __restrict__ Wih,
    const float* __restrict__ bih, const float* __restrict__ bhh)
{
    extern __shared__ float sm1[];
    float* wsg  = sm1;                   // [64][512] k-major
    float* bsum = wsg + 64 * 512;        // [512]
    float* xs   = bsum + 512;            // [64 k][68 rows] padded

    const int tid = threadIdx.x;

    for (int idx = tid; idx < 64 * 512; idx += 512) {
        int k = idx >> 9, c = idx & 511;
        wsg[idx] = Wih[c * 64 + k];
    }
    bsum[tid] = bih[tid] + bhh[tid];
    __syncthreads();

    const int lane = tid & 31, wrp = tid >> 5;
    const int r0 = (wrp & 7) * 8;
    const int cb = (wrp >> 3) * 256 + lane * 4;

    u64 bp[4];
    {
        float4 t0 = *(const float4*)&bsum[cb];
        float4 t1 = *(const float4*)&bsum[cb + 128];
        bp[0] = pk(t0.x, t0.y); bp[1] = pk(t0.z, t0.w);
        bp[2] = pk(t1.x, t1.y); bp[3] = pk(t1.z, t1.w);
    }

    for (int tile = blockIdx.x; tile < BT / 64; tile += gridDim.x) {
        __syncthreads();
        for (int idx = tid; idx < 64 * 64; idx += 512) {
            int r = idx >> 6, k = idx & 63;
            xs[k * 68 + r] = x[(size_t)tile * 64 * 64 + idx];
        }
        __syncthreads();

        u64 acc[8][4];
        #pragma unroll
        for (int ri = 0; ri < 8; ri++) {
            acc[ri][0] = bp[0]; acc[ri][1] = bp[1];
            acc[ri][2] = bp[2]; acc[ri][3] = bp[3];
        }

        #pragma unroll 8
        for (int k = 0; k < 64; k++) {
            // direct u64 pair loads — little-endian makes these pk(w[i],w[i+1])
            ulonglong2 wv0 = *(const ulonglong2*)&wsg[k * 512 + cb];
            ulonglong2 wv1 = *(const ulonglong2*)&wsg[k * 512 + cb + 128];
            float4 xa = *(const float4*)&xs[k * 68 + r0];
            float4 xb = *(const float4*)&xs[k * 68 + r0 + 4];
            float xv[8] = {xa.x, xa.y, xa.z, xa.w, xb.x, xb.y, xb.z, xb.w};
            #pragma unroll
            for (int ri = 0; ri < 8; ri++) {
                u64 xx = pk(xv[ri], xv[ri]);
                fma2(acc[ri][0], wv0.x, xx); fma2(acc[ri][1], wv0.y, xx);
                fma2(acc[ri][2], wv1.x, xx); fma2(acc[ri][3], wv1.y, xx);
            }
        }

        #pragma unroll
        for (int ri = 0; ri < 8; ri++) {
            size_t row = (size_t)tile * 64 + r0 + ri;
            float a0,a1,a2,a3,a4,a5,a6,a7;
            upk(acc[ri][0], a0, a1); upk(acc[ri][1], a2, a3);
            upk(acc[ri][2], a4, a5); upk(acc[ri][3], a6, a7);
            *(float4*)&g_xproj[row * GG + cb]       = make_float4(a0,a1,a2,a3);
            *(float4*)&g_xproj[row * GG + cb + 128] = make_float4(a4,a5,a6,a7);
        }
    }
}

// ---------------------------------------------------------------------------
// Phase 2: LSTM recurrence. One CTA per batch (128 CTAs, one wave).
// 256 threads; thread tid owns gate rows tid and tid+256; threads tid and
// tid+128 together hold all 4 gates of hidden unit jh = tid & 127.
// W_hh[row][0:112] in registers (2 x 56 u64); [112:128) in SMEM as
// ulonglong2 [4][512] -> 8 LDS.128/thread. h broadcast as LDS.128 pairs.
// Activations gathered via one float4 {i,g,f,o} per hidden unit.
// SMEM: ws2 4*512*16 = 32768, h 2*128*4 = 1024, gQ 128*16 = 2048 -> 35840B
// ---------------------------------------------------------------------------
__global__ __launch_bounds__(256, 1) void lstm_kernel(
    const float* __restrict__ Whh, const float* __restrict__ h0,
    const float* __restrict__ c0, float* __restrict__ out)
{
    extern __shared__ char sm2c[];
    ulonglong2* ws2 = (ulonglong2*)sm2c;                 // [NSQ][512]
    float*      h_s = (float*)(sm2c + NSQ * 512 * 16);   // [2][128]
    float*      gQ  = h_s + 2 * HH;                      // [128][4] {i,g,f,o}

    const int tid = threadIdx.x;          // 0..255
    const int jh  = tid & 127;            // hidden unit index
    const int b   = blockIdx.x;
    const int rA  = tid;                  // row A: i (tid<128) or f
    const int rB  = tid + 256;            // row B: g (tid<128) or o

    // --- register weights: rows rA, rB cols [0,112) as 56 u64 each ---
    u64 wA[REGK / 2], wB[REGK / 2];
    {
        const float* a  = Whh + rA * HH;
        const float* bq = Whh + rB * HH;
        #pragma unroll
        for (int q = 0; q < REGK / 4; q++) {
            float4 v = *(const float4*)&a[4 * q];
            wA[2 * q] = pk(v.x, v.y); wA[2 * q + 1] = pk(v.z, v.w);
            float4 w = *(const float4*)&bq[4 * q];
            wB[2 * q] = pk(w.x, w.y); wB[2 * q + 1] = pk(w.z, w.w);
        }
    }
    // --- SMEM weights: ws2[q*512 + r] = cols [112+4q, 112+4q+3] of row r ---
    for (int idx = tid; idx < NSQ * 512; idx += 256) {
        int q = idx >> 9, r = idx & 511;
        float4 v = *(const float4*)&Whh[r * HH + REGK + 4 * q];
        ulonglong2 u; u.x = pk(v.x, v.y); u.y = pk(v.z, v.w);
        ws2[idx] = u;
    }
    // --- initial state (both partner threads carry c redundantly) ---
    float c = c0[b * HH + jh];
    if (tid < HH) h_s[tid] = h0[b * HH + tid];
    __syncthreads();

    const float* xp = g_xproj + (size_t)b * TT * GG;
    float* enc = out + BB * HH + (size_t)b * TT * HH;

    int p = 0;
    float xgA = xp[rA];                    // prefetch t = 0
    float xgB = xp[rB];
    for (int t = 0; t < TT; t++) {
        float xa = xgA, xb = xgB;
        if (t + 1 < TT) {                  // prefetch next step
            xgA = xp[(size_t)(t + 1) * GG + rA];
            xgB = xp[(size_t)(t + 1) * GG + rB];
        }

        const ulonglong2* hb2 = (const ulonglong2*)&h_s[p * HH];  // 32 pairs
        u64 aA0 = 0ULL, aA1 = 0ULL, aB0 = 0ULL, aB1 = 0ULL;

        // register part: k in [0, 112) -> 28 LDS.128 broadcasts
        #pragma unroll
        for (int q = 0; q < REGK / 4; q++) {
            ulonglong2 hh = hb2[q];
            fma2(aA0, wA[2 * q],     hh.x); fma2(aB0, wB[2 * q],     hh.x);
            fma2(aA1, wA[2 * q + 1], hh.y); fma2(aB1, wB[2 * q + 1], hh.y);
        }
        // SMEM part: k in [112, 128) -> 4 broadcasts + 8 weight LDS.128
        #pragma unroll
        for (int q = 0; q < NSQ; q++) {
            ulonglong2 hh = hb2[REGK / 4 + q];
            ulonglong2 wa = ws2[q * 512 + rA];
            ulonglong2 wb = ws2[q * 512 + rB];
            fma2(aA0, wa.x, hh.x); fma2(aA1, wa.y, hh.y);
            fma2(aB0, wb.x, hh.x); fma2(aB1, wb.y, hh.y);
        }

        float s0, s1, s2, s3;
        upk(aA0, s0, s1); upk(aA1, s2, s3);
        float gA = xa + (s0 + s1) + (s2 + s3);
        upk(aB0, s0, s1); upk(aB1, s2, s3);
        float gB = xb + (s0 + s1) + (s2 + s3);

        // distributed activations (HW tanh), gathered as float4 {i,g,f,o}:
        // tid<128: rows (i, g) -> gQ[jh].xy ; tid>=128: rows (f, o) -> gQ[jh].zw
        float act0 = sigmoid_ap(gA);
        float act1 = (tid < 128) ? tanh_ap(gB) : sigmoid_ap(gB);
        {
            float2* dst = (float2*)&gQ[4 * jh + ((tid < 128) ? 0 : 2)];
            *dst = make_float2(act0, act1);
        }
        __syncthreads();

        // phase B (redundant across the partner pair; c stays consistent)
        float4 q4 = *(const float4*)&gQ[4 * jh];   // {i, g, f, o}
        c = q4.z * c + q4.x * q4.y;
        if (tid < 128) {
            float hn = q4.w * tanh_ap(c);
            h_s[(p ^ 1) * HH + jh] = hn;
            enc[(size_t)t * HH + jh] = hn;
        }
        __syncthreads();
        p ^= 1;
    }

    if (tid < HH) out[b * HH + tid] = h_s[p * HH + tid];   // h_last
}

extern "C" void kernel_launch(void* const* d_in, const int* in_sizes, int n_in,
                              void* d_out, int out_size) {
    const float* x    = (const float*)d_in[0];   // [B,T,I]
    const float* h0   = (const float*)d_in[1];   // [B,H]
    const float* c0   = (const float*)d_in[2];   // [B,H]
    const float* Wih  = (const float*)d_in[3];   // [4H,I]
    const float* Whh  = (const float*)d_in[4];   // [4H,H]
    const float* bih  = (const float*)d_in[5];   // [4H]
    const float* bhh  = (const float*)d_in[6];   // [4H]
    float* out = (float*)d_out;                  // [B*H] h_last, then [B,T,H]

    constexpr int SMEM1 = (64 * 512 + 512 + 64 * 68) * 4;              // 150528
    constexpr int SMEM2 = NSQ * 512 * 16 + 2 * HH * 4 + HH * 16;       // 35840

    cudaFuncSetAttribute(xproj_kernel,
        cudaFuncAttributeMaxDynamicSharedMemorySize, SMEM1);
    cudaFuncSetAttribute(lstm_kernel,
        cudaFuncAttributeMaxDynamicSharedMemorySize, SMEM2);

    xproj_kernel<<<148, 512, SMEM1>>>(x, Wih, bih, bhh);
    lstm_kernel<<<BB, 256, SMEM2>>>(Whh, h0, c0, out);
}

// round 14
// speedup vs baseline: 1.4256x; 1.4256x over previous
#include <cuda_runtime.h>
#include <cuda_bf16.h>
#include <cstdint>
#include <cstddef>

#define BB 128
#define TT 2048
#define II 64
#define HH 128
#define GG 512                 // 4*H
#define BT (BB * TT)

// ---- recurrence config: 256 threads, 2 rows/thread --------------------------
#define REGK 104               // W_hh cols per row held in registers (RF boundary)
#define SMEMK (HH - REGK)      // 24 cols in SMEM
#define NSQ (SMEMK / 4)        // 6 ulonglong2 groups per row

typedef unsigned long long u64;

// 512MB scratch for x_proj[row][g], row = b*T + t, g in [0,512)
__device__ float g_xproj[(size_t)BT * GG];

__device__ __forceinline__ u64 pk(float lo, float hi) {
    u64 r; asm("mov.b64 %0,{%1,%2};" : "=l"(r) : "f"(lo), "f"(hi)); return r;
}
__device__ __forceinline__ void upk(u64 v, float& lo, float& hi) {
    asm("mov.b64 {%0,%1},%2;" : "=f"(lo), "=f"(hi) : "l"(v));
}
// packed fp32x2 FMA (sm_103a): d.lo += a.lo*b.lo ; d.hi += a.hi*b.hi
__device__ __forceinline__ void fma2(u64& d, u64 a, u64 b) {
    asm("fma.rn.f32x2 %0,%1,%2,%0;" : "+l"(d) : "l"(a), "l"(b));
}

// HW tanh (MUFU-class single op, rel err ~2^-10.8)
__device__ __forceinline__ float tanh_ap(float x) {
    float y; asm("tanh.approx.f32 %0, %1;" : "=f"(y) : "f"(x)); return y;
}
__device__ __forceinline__ float sigmoid_ap(float x) {
    return fmaf(0.5f, tanh_ap(0.5f * x), 0.5f);
}

// ---------------------------------------------------------------------------
// Phase 1: g_xproj[row][512] = W_ih @ x[row] + (b_ih + b_hh)
// Persistent CTAs; W_ih k-major in SMEM; 64-row x tiles k-major in SMEM.
// Weights loaded as ulonglong2 (pre-paired f32x2, no repack MOVs).
// ---------------------------------------------------------------------------
__global__ __launch_bounds__(512, 1) void xproj_kernel(
    const float* __restrict__ x, const float* __restrict__ Wih,
    const float* __restrict__ bih, const float* __restrict__ bhh)
{
    extern __shared__ float sm1[];
    float* wsg  = sm1;                   // [64][512] k-major
    float* bsum = wsg + 64 * 512;        // [512]
    float* xs   = bsum + 512;            // [64 k][68 rows] padded

    const int tid = threadIdx.x;

    for (int idx = tid; idx < 64 * 512; idx += 512) {
        int k = idx >> 9, c = idx & 511;
        wsg[idx] = Wih[c * 64 + k];
    }
    bsum[tid] = bih[tid] + bhh[tid];
    __syncthreads();

    const int lane = tid & 31, wrp = tid >> 5;
    const int r0 = (wrp & 7) * 8;
    const int cb = (wrp >> 3) * 256 + lane * 4;

    u64 bp[4];
    {
        float4 t0 = *(const float4*)&bsum[cb];
        float4 t1 = *(const float4*)&bsum[cb + 128];
        bp[0] = pk(t0.x, t0.y); bp[1] = pk(t0.z, t0.w);
        bp[2] = pk(t1.x, t1.y); bp[3] = pk(t1.z, t1.w);
    }

    for (int tile = blockIdx.x; tile < BT / 64; tile += gridDim.x) {
        __syncthreads();
        for (int idx = tid; idx < 64 * 64; idx += 512) {
            int r = idx >> 6, k = idx & 63;
            xs[k * 68 + r] = x[(size_t)tile * 64 * 64 + idx];
        }
        __syncthreads();

        u64 acc[8][4];
        #pragma unroll
        for (int ri = 0; ri < 8; ri++) {
            acc[ri][0] = bp[0]; acc[ri][1] = bp[1];
            acc[ri][2] = bp[2]; acc[ri][3] = bp[3];
        }

        #pragma unroll 8
        for (int k = 0; k < 64; k++) {
            // direct u64 pair loads — little-endian makes these pk(w[i],w[i+1])
            ulonglong2 wv0 = *(const ulonglong2*)&wsg[k * 512 + cb];
            ulonglong2 wv1 = *(const ulonglong2*)&wsg[k * 512 + cb + 128];
            float4 xa = *(const float4*)&xs[k * 68 + r0];
            float4 xb = *(const float4*)&xs[k * 68 + r0 + 4];
            float xv[8] = {xa.x, xa.y, xa.z, xa.w, xb.x, xb.y, xb.z, xb.w};
            #pragma unroll
            for (int ri = 0; ri < 8; ri++) {
                u64 xx = pk(xv[ri], xv[ri]);
                fma2(acc[ri][0], wv0.x, xx); fma2(acc[ri][1], wv0.y, xx);
                fma2(acc[ri][2], wv1.x, xx); fma2(acc[ri][3], wv1.y, xx);
            }
        }

        #pragma unroll
        for (int ri = 0; ri < 8; ri++) {
            size_t row = (size_t)tile * 64 + r0 + ri;
            float a0,a1,a2,a3,a4,a5,a6,a7;
            upk(acc[ri][0], a0, a1); upk(acc[ri][1], a2, a3);
            upk(acc[ri][2], a4, a5); upk(acc[ri][3], a6, a7);
            *(float4*)&g_xproj[row * GG + cb]       = make_float4(a0,a1,a2,a3);
            *(float4*)&g_xproj[row * GG + cb + 128] = make_float4(a4,a5,a6,a7);
        }
    }
}

// ---------------------------------------------------------------------------
// Phase 2: LSTM recurrence (R12 structure = measured best, + float4 gather).
// One CTA per batch (128 CTAs, one wave). 256 threads; thread tid owns gate
// rows tid and tid+256; threads tid and tid+128 together hold all 4 gates of
// hidden unit jh = tid & 127.
// W_hh[row][0:104] in registers (2 x 52 u64); [104:128) in SMEM as
// ulonglong2 [6][512] -> 12 LDS.128/thread. h broadcast as LDS.128 pairs.
// Activations gathered via one float4 {i,g,f,o} per hidden unit.
// SMEM: ws2 6*512*16 = 49152, h 2*128*4 = 1024, gQ 128*16 = 2048 -> 52224B
// ---------------------------------------------------------------------------
__global__ __launch_bounds__(256, 1) void lstm_kernel(
    const float* __restrict__ Whh, const float* __restrict__ h0,
    const float* __restrict__ c0, float* __restrict__ out)
{
    extern __shared__ char sm2c[];
    ulonglong2* ws2 = (ulonglong2*)sm2c;                 // [NSQ][512]
    float*      h_s = (float*)(sm2c + NSQ * 512 * 16);   // [2][128]
    float*      gQ  = h_s + 2 * HH;                      // [128][4] {i,g,f,o}

    const int tid = threadIdx.x;          // 0..255
    const int jh  = tid & 127;            // hidden unit index
    const int b   = blockIdx.x;
    const int rA  = tid;                  // row A: i (tid<128) or f
    const int rB  = tid + 256;            // row B: g (tid<128) or o

    // --- register weights: rows rA, rB cols [0,104) as 52 u64 each ---
    u64 wA[REGK / 2], wB[REGK / 2];
    {
        const float* a  = Whh + rA * HH;
        const float* bq = Whh + rB * HH;
        #pragma unroll
        for (int q = 0; q < REGK / 4; q++) {
            float4 v = *(const float4*)&a[4 * q];
            wA[2 * q] = pk(v.x, v.y); wA[2 * q + 1] = pk(v.z, v.w);
            float4 w = *(const float4*)&bq[4 * q];
            wB[2 * q] = pk(w.x, w.y); wB[2 * q + 1] = pk(w.z, w.w);
        }
    }
    // --- SMEM weights: ws2[q*512 + r] = cols [104+4q, 104+4q+3] of row r ---
    for (int idx = tid; idx < NSQ * 512; idx += 256) {
        int q = idx >> 9, r = idx & 511;
        float4 v = *(const float4*)&Whh[r * HH + REGK + 4 * q];
        ulonglong2 u; u.x = pk(v.x, v.y); u.y = pk(v.z, v.w);
        ws2[idx] = u;
    }
    // --- initial state (both partner threads carry c redundantly) ---
    float c = c0[b * HH + jh];
    if (tid < HH) h_s[tid] = h0[b * HH + tid];
    __syncthreads();

    const float* xp = g_xproj + (size_t)b * TT * GG;
    float* enc = out + BB * HH + (size_t)b * TT * HH;

    int p = 0;
    float xgA = xp[rA];                    // prefetch t = 0
    float xgB = xp[rB];
    for (int t = 0; t < TT; t++) {
        float xa = xgA, xb = xgB;
        if (t + 1 < TT) {                  // prefetch next step
            xgA = xp[(size_t)(t + 1) * GG + rA];
            xgB = xp[(size_t)(t + 1) * GG + rB];
        }

        const ulonglong2* hb2 = (const ulonglong2*)&h_s[p * HH];  // 32 pairs
        u64 aA0 = 0ULL, aA1 = 0ULL, aB0 = 0ULL, aB1 = 0ULL;

        // register part: k in [0, 104) -> 26 LDS.128 broadcasts
        #pragma unroll
        for (int q = 0; q < REGK / 4; q++) {
            ulonglong2 hh = hb2[q];
            fma2(aA0, wA[2 * q],     hh.x); fma2(aB0, wB[2 * q],     hh.x);
            fma2(aA1, wA[2 * q + 1], hh.y); fma2(aB1, wB[2 * q + 1], hh.y);
        }
        // SMEM part: k in [104, 128) -> 6 broadcasts + 12 weight LDS.128
        #pragma unroll
        for (int q = 0; q < NSQ; q++) {
            ulonglong2 hh = hb2[REGK / 4 + q];
            ulonglong2 wa = ws2[q * 512 + rA];
            ulonglong2 wb = ws2[q * 512 + rB];
            fma2(aA0, wa.x, hh.x); fma2(aA1, wa.y, hh.y);
            fma2(aB0, wb.x, hh.x); fma2(aB1, wb.y, hh.y);
        }

        float s0, s1, s2, s3;
        upk(aA0, s0, s1); upk(aA1, s2, s3);
        float gA = xa + (s0 + s1) + (s2 + s3);
        upk(aB0, s0, s1); upk(aB1, s2, s3);
        float gB = xb + (s0 + s1) + (s2 + s3);

        // distributed activations (HW tanh), gathered as float4 {i,g,f,o}:
        // tid<128: rows (i, g) -> gQ[jh].xy ; tid>=128: rows (f, o) -> gQ[jh].zw
        float act0 = sigmoid_ap(gA);
        float act1 = (tid < 128) ? tanh_ap(gB) : sigmoid_ap(gB);
        {
            float2* dst = (float2*)&gQ[4 * jh + ((tid < 128) ? 0 : 2)];
            *dst = make_float2(act0, act1);
        }
        __syncthreads();

        // phase B (redundant across the partner pair; c stays consistent)
        float4 q4 = *(const float4*)&gQ[4 * jh];   // {i, g, f, o}
        c = q4.z * c + q4.x * q4.y;
        if (tid < 128) {
            float hn = q4.w * tanh_ap(c);
            h_s[(p ^ 1) * HH + jh] = hn;
            enc[(size_t)t * HH + jh] = hn;
        }
        __syncthreads();
        p ^= 1;
    }

    if (tid < HH) out[b * HH + tid] = h_s[p * HH + tid];   // h_last
}

extern "C" void kernel_launch(void* const* d_in, const int* in_sizes, int n_in,
                              void* d_out, int out_size) {
    const float* x    = (const float*)d_in[0];   // [B,T,I]
    const float* h0   = (const float*)d_in[1];   // [B,H]
    const float* c0   = (const float*)d_in[2];   // [B,H]
    const float* Wih  = (const float*)d_in[3];   // [4H,I]
    const float* Whh  = (const float*)d_in[4];   // [4H,H]
    const float* bih  = (const float*)d_in[5];   // [4H]
    const float* bhh  = (const float*)d_in[6];   // [4H]
    float* out = (float*)d_out;                  // [B*H] h_last, then [B,T,H]

    constexpr int SMEM1 = (64 * 512 + 512 + 64 * 68) * 4;          // 150528
    constexpr int SMEM2 = NSQ * 512 * 16 + 2 * HH * 4 + HH * 16;   // 52224

    cudaFuncSetAttribute(xproj_kernel,
        cudaFuncAttributeMaxDynamicSharedMemorySize, SMEM1);
    cudaFuncSetAttribute(lstm_kernel,
        cudaFuncAttributeMaxDynamicSharedMemorySize, SMEM2);

    xproj_kernel<<<148, 512, SMEM1>>>(x, Wih, bih, bhh);
    lstm_kernel<<<BB, 256, SMEM2>>>(Whh, h0, c0, out);
}